// round 2
// baseline (speedup 1.0000x reference)
#include <cuda_runtime.h>
#include <math.h>

#define B_  2
#define L_  2048
#define E_  1024
#define H_  16
#define DH_ 64
#define M_  (B_*L_)          // 4096 rows
#define AST 68               // attention smem row stride (64 + 4 pad, float4-aligned)
#define ATTN_SMEM (4*64*AST*4)

// ---------------- scratch (device globals; no allocation allowed) ----------
__device__ float g_Q[(size_t)B_*H_*L_*DH_];
__device__ float g_K[(size_t)B_*H_*L_*DH_];
__device__ float g_V[(size_t)B_*H_*L_*DH_];
__device__ float g_CTX[(size_t)M_*E_];
__device__ float g_PROJ[(size_t)M_*E_];

// ---------------- GEMM: out = A[M,K] @ W[N,K]^T + bias ---------------------
// MODE 0: scatter to [B,H,L,DH] head-split layout (Q/K/V projections)
// MODE 1: plain [M,N] + residual (output projection)
template<int MODE>
__global__ __launch_bounds__(256) void gemm_kernel(
    const float* __restrict__ A, const float* __restrict__ W,
    const float* __restrict__ bias, const float* __restrict__ resid,
    float* __restrict__ out, int Kn, int Nn)
{
    __shared__ float sA[64][17];
    __shared__ float sB[64][17];
    const int t  = threadIdx.x;
    const int m0 = blockIdx.y << 6;
    const int n0 = blockIdx.x << 6;
    const int r0 = (t >> 4) << 2;   // 4 consecutive output rows
    const int j  = t & 15;          // column lane; cols are j + 16*c
    const int lr = t >> 2;          // loader row
    const int lk = (t & 3) << 2;    // loader k-offset (float4)

    float acc[4][4] = {};
    const float* Ap = A + (size_t)(m0 + lr) * Kn + lk;
    const float* Wp = W + (size_t)(n0 + lr) * Kn + lk;

    for (int k0 = 0; k0 < Kn; k0 += 16) {
        float4 a4 = *(const float4*)(Ap + k0);
        float4 b4 = *(const float4*)(Wp + k0);
        __syncthreads();
        sA[lr][lk] = a4.x; sA[lr][lk+1] = a4.y; sA[lr][lk+2] = a4.z; sA[lr][lk+3] = a4.w;
        sB[lr][lk] = b4.x; sB[lr][lk+1] = b4.y; sB[lr][lk+2] = b4.z; sB[lr][lk+3] = b4.w;
        __syncthreads();
        #pragma unroll
        for (int kk = 0; kk < 16; kk++) {
            float av[4], bv[4];
            #pragma unroll
            for (int i = 0; i < 4; i++) av[i] = sA[r0 + i][kk];
            #pragma unroll
            for (int c = 0; c < 4; c++) bv[c] = sB[j + (c << 4)][kk];
            #pragma unroll
            for (int i = 0; i < 4; i++)
                #pragma unroll
                for (int c = 0; c < 4; c++)
                    acc[i][c] += av[i] * bv[c];
        }
    }

    #pragma unroll
    for (int i = 0; i < 4; i++) {
        #pragma unroll
        for (int c = 0; c < 4; c++) {
            const int m = m0 + r0 + i;
            const int n = n0 + j + (c << 4);
            float v = acc[i][c] + bias[n];
            if (MODE == 1) {
                const size_t idx = (size_t)m * Nn + n;
                out[idx] = v + resid[idx];
            } else {
                const int b = m >> 11;          // L_ = 2048
                const int l = m & (L_ - 1);
                const int h = n >> 6;           // DH_ = 64
                const int d = n & 63;
                out[(((((size_t)b * H_ + h) << 11) + l) << 6) + d] = v;
            }
        }
    }
}

// ---------------- flash attention (fp32, online softmax) -------------------
// grid: (L/64, H, B), block 256. Each block: 64 q-rows, iterate 64-col k-tiles.
__global__ __launch_bounds__(256) void attn_kernel(
    const float* __restrict__ Qg, const float* __restrict__ Kg,
    const float* __restrict__ Vg, const unsigned char* __restrict__ mask,
    float* __restrict__ CTX)
{
    extern __shared__ float sm[];
    float* sQ = sm;
    float* sK = sm + 64 * AST;
    float* sV = sm + 2 * 64 * AST;
    float* sP = sm + 3 * 64 * AST;

    const int t  = threadIdx.x;
    const int qt = blockIdx.x;
    const int h  = blockIdx.y;
    const int b  = blockIdx.z;

    const float* Qb = Qg + (((size_t)b * H_ + h) * L_ + (qt << 6)) * DH_;
    const float* Kb = Kg + ((size_t)b * H_ + h) * L_ * DH_;
    const float* Vb = Vg + ((size_t)b * H_ + h) * L_ * DH_;

    // load Q tile (64x64) — float4, 16B-aligned (AST*4 = 272 bytes, 16B mult)
    #pragma unroll
    for (int i = 0; i < 4; i++) {
        int idx = t + (i << 8);
        int row = idx >> 4;
        int c4  = (idx & 15) << 2;
        *(float4*)&sQ[row * AST + c4] = *(const float4*)&Qb[(row << 6) + c4];
    }

    const int r0 = (t >> 4) << 2;
    const int j  = t & 15;

    float m_run[4], l_run[4], accO[4][4];
    #pragma unroll
    for (int i = 0; i < 4; i++) {
        m_run[i] = -1e30f; l_run[i] = 0.f;
        #pragma unroll
        for (int c = 0; c < 4; c++) accO[i][c] = 0.f;
    }

    const size_t mrow = ((size_t)b * L_ + (qt << 6) + r0) * L_;

    for (int kt = 0; kt < L_ / 64; kt++) {
        __syncthreads();   // prior PV reads of sK/sV done
        const float* Kt = Kb + ((size_t)kt << 6) * DH_;
        const float* Vt = Vb + ((size_t)kt << 6) * DH_;
        #pragma unroll
        for (int i = 0; i < 4; i++) {
            int idx = t + (i << 8);
            int row = idx >> 4;
            int c4  = (idx & 15) << 2;
            *(float4*)&sK[row * AST + c4] = *(const float4*)&Kt[(row << 6) + c4];
            *(float4*)&sV[row * AST + c4] = *(const float4*)&Vt[(row << 6) + c4];
        }
        __syncthreads();

        // S = Q K^T for 4x4 microtile; cols j, j+16, j+32, j+48 (bank-phase safe)
        float S[4][4] = {};
        #pragma unroll
        for (int d = 0; d < 64; d += 4) {
            float4 qv[4], kv[4];
            #pragma unroll
            for (int i = 0; i < 4; i++) qv[i] = *(const float4*)&sQ[(r0 + i) * AST + d];
            #pragma unroll
            for (int c = 0; c < 4; c++) kv[c] = *(const float4*)&sK[(j + (c << 4)) * AST + d];
            #pragma unroll
            for (int i = 0; i < 4; i++)
                #pragma unroll
                for (int c = 0; c < 4; c++)
                    S[i][c] += qv[i].x * kv[c].x + qv[i].y * kv[c].y
                             + qv[i].z * kv[c].z + qv[i].w * kv[c].w;
        }

        // scale (1/sqrt(DH)) + mask
        #pragma unroll
        for (int i = 0; i < 4; i++)
            #pragma unroll
            for (int c = 0; c < 4; c++) {
                float s = S[i][c] * 0.125f;
                if (mask[mrow + (size_t)i * L_ + (kt << 6) + j + (c << 4)]) s = -1e30f;
                S[i][c] = s;
            }

        // row max across the 16-lane column group
        float mt[4];
        #pragma unroll
        for (int i = 0; i < 4; i++)
            mt[i] = fmaxf(fmaxf(S[i][0], S[i][1]), fmaxf(S[i][2], S[i][3]));
        #pragma unroll
        for (int off = 8; off >= 1; off >>= 1)
            #pragma unroll
            for (int i = 0; i < 4; i++)
                mt[i] = fmaxf(mt[i], __shfl_xor_sync(0xffffffffu, mt[i], off));

        float alpha[4], rs[4];
        #pragma unroll
        for (int i = 0; i < 4; i++) {
            float mn = fmaxf(m_run[i], mt[i]);
            alpha[i] = __expf(m_run[i] - mn);
            m_run[i] = mn;
            rs[i] = 0.f;
            #pragma unroll
            for (int c = 0; c < 4; c++) {
                S[i][c] = __expf(S[i][c] - mn);
                rs[i] += S[i][c];
            }
        }
        #pragma unroll
        for (int off = 8; off >= 1; off >>= 1)
            #pragma unroll
            for (int i = 0; i < 4; i++)
                rs[i] += __shfl_xor_sync(0xffffffffu, rs[i], off);
        #pragma unroll
        for (int i = 0; i < 4; i++) {
            l_run[i] = l_run[i] * alpha[i] + rs[i];
            #pragma unroll
            for (int c = 0; c < 4; c++) accO[i][c] *= alpha[i];
        }

        // stage P
        #pragma unroll
        for (int i = 0; i < 4; i++)
            #pragma unroll
            for (int c = 0; c < 4; c++)
                sP[(r0 + i) * AST + j + (c << 4)] = S[i][c];
        __syncthreads();

        // O += P @ V
        #pragma unroll 4
        for (int jj = 0; jj < 64; jj++) {
            float pv[4], vv[4];
            #pragma unroll
            for (int i = 0; i < 4; i++) pv[i] = sP[(r0 + i) * AST + jj];
            #pragma unroll
            for (int c = 0; c < 4; c++) vv[c] = sV[jj * AST + j + (c << 4)];
            #pragma unroll
            for (int i = 0; i < 4; i++)
                #pragma unroll
                for (int c = 0; c < 4; c++)
                    accO[i][c] += pv[i] * vv[c];
        }
    }

    #pragma unroll
    for (int i = 0; i < 4; i++) {
        const int l = (qt << 6) + r0 + i;
        const float inv = 1.0f / l_run[i];
        #pragma unroll
        for (int c = 0; c < 4; c++)
            CTX[((size_t)b * L_ + l) * E_ + (h << 6) + j + (c << 4)] = accO[i][c] * inv;
    }
}

// ---------------- LayerNorm over E=1024, one row per block -----------------
__global__ __launch_bounds__(256) void ln_kernel(
    const float* __restrict__ X, const float* __restrict__ gamma,
    const float* __restrict__ beta, float* __restrict__ out)
{
    __shared__ float red[8];
    __shared__ float s_mu, s_rstd;
    const int row = blockIdx.x;
    const int t = threadIdx.x;

    float4 v = ((const float4*)(X + (size_t)row * E_))[t];
    float s = v.x + v.y + v.z + v.w;
    #pragma unroll
    for (int off = 16; off >= 1; off >>= 1) s += __shfl_xor_sync(0xffffffffu, s, off);
    if ((t & 31) == 0) red[t >> 5] = s;
    __syncthreads();
    if (t == 0) {
        float tot = 0.f;
        #pragma unroll
        for (int k = 0; k < 8; k++) tot += red[k];
        s_mu = tot * (1.0f / E_);
    }
    __syncthreads();
    const float mu = s_mu;

    float dx = v.x - mu, dy = v.y - mu, dz = v.z - mu, dw = v.w - mu;
    float sq = dx * dx + dy * dy + dz * dz + dw * dw;
    #pragma unroll
    for (int off = 16; off >= 1; off >>= 1) sq += __shfl_xor_sync(0xffffffffu, sq, off);
    __syncthreads();                       // protect red reuse
    if ((t & 31) == 0) red[t >> 5] = sq;
    __syncthreads();
    if (t == 0) {
        float tot = 0.f;
        #pragma unroll
        for (int k = 0; k < 8; k++) tot += red[k];
        s_rstd = rsqrtf(tot * (1.0f / E_) + 1e-6f);
    }
    __syncthreads();
    const float rstd = s_rstd;

    float4 g  = ((const float4*)gamma)[t];
    float4 be = ((const float4*)beta)[t];
    float4 o;
    o.x = dx * rstd * g.x + be.x;
    o.y = dy * rstd * g.y + be.y;
    o.z = dz * rstd * g.z + be.z;
    o.w = dw * rstd * g.w + be.w;
    ((float4*)(out + (size_t)row * E_))[t] = o;
}

// ---------------- launch ---------------------------------------------------
extern "C" void kernel_launch(void* const* d_in, const int* in_sizes, int n_in,
                              void* d_out, int out_size)
{
    const float* xq    = (const float*)d_in[0];
    const float* xk    = (const float*)d_in[1];
    const float* xv    = (const float*)d_in[2];
    const unsigned char* mask = (const unsigned char*)d_in[3];
    const float* Wq = (const float*)d_in[4];
    const float* bq = (const float*)d_in[5];
    const float* Wk = (const float*)d_in[6];
    const float* bk = (const float*)d_in[7];
    const float* Wv = (const float*)d_in[8];
    const float* bv = (const float*)d_in[9];
    const float* Wo = (const float*)d_in[10];
    const float* bo = (const float*)d_in[11];
    const float* gamma = (const float*)d_in[12];
    const float* beta  = (const float*)d_in[13];
    float* out = (float*)d_out;

    float *dQ, *dK, *dV, *dCTX, *dPROJ;
    cudaGetSymbolAddress((void**)&dQ,    g_Q);
    cudaGetSymbolAddress((void**)&dK,    g_K);
    cudaGetSymbolAddress((void**)&dV,    g_V);
    cudaGetSymbolAddress((void**)&dCTX,  g_CTX);
    cudaGetSymbolAddress((void**)&dPROJ, g_PROJ);

    cudaFuncSetAttribute(attn_kernel,
                         cudaFuncAttributeMaxDynamicSharedMemorySize, ATTN_SMEM);

    dim3 ggrid(E_ / 64, M_ / 64);

    gemm_kernel<0><<<ggrid, 256>>>(xq, Wq, bq, nullptr, dQ, E_, E_);
    gemm_kernel<0><<<ggrid, 256>>>(xk, Wk, bk, nullptr, dK, E_, E_);
    gemm_kernel<0><<<ggrid, 256>>>(xv, Wv, bv, nullptr, dV, E_, E_);

    attn_kernel<<<dim3(L_ / 64, H_, B_), 256, ATTN_SMEM>>>(dQ, dK, dV, mask, dCTX);

    gemm_kernel<1><<<ggrid, 256>>>(dCTX, Wo, bo, xq, dPROJ, E_, E_);

    ln_kernel<<<M_, 256>>>(dPROJ, gamma, beta, out);
}

// round 3
// speedup vs baseline: 1.0005x; 1.0005x over previous
#include <cuda_runtime.h>
#include <math.h>

#define B_  2
#define L_  2048
#define E_  1024
#define H_  16
#define DH_ 64
#define M_  (B_*L_)          // 4096 rows
#define AST 68               // attention smem row stride (64 + 4 pad, float4-aligned)
#define ATTN_SMEM (4*64*AST*4)

// ---------------- scratch (device globals; no allocation allowed) ----------
__device__ float g_Q[(size_t)B_*H_*L_*DH_];
__device__ float g_K[(size_t)B_*H_*L_*DH_];
__device__ float g_V[(size_t)B_*H_*L_*DH_];
__device__ float g_CTX[(size_t)M_*E_];
__device__ float g_PROJ[(size_t)M_*E_];

// ---------------- GEMM: out = A[M,K] @ W[N,K]^T + bias ---------------------
// MODE 0: scatter to [B,H,L,DH] head-split layout (Q/K/V projections)
// MODE 1: plain [M,N] + residual (output projection)
template<int MODE>
__global__ __launch_bounds__(256) void gemm_kernel(
    const float* __restrict__ A, const float* __restrict__ W,
    const float* __restrict__ bias, const float* __restrict__ resid,
    float* __restrict__ out, int Kn, int Nn)
{
    __shared__ float sA[64][17];
    __shared__ float sB[64][17];
    const int t  = threadIdx.x;
    const int m0 = blockIdx.y << 6;
    const int n0 = blockIdx.x << 6;
    const int r0 = (t >> 4) << 2;   // 4 consecutive output rows
    const int j  = t & 15;          // column lane; cols are j + 16*c
    const int lr = t >> 2;          // loader row
    const int lk = (t & 3) << 2;    // loader k-offset (float4)

    float acc[4][4] = {};
    const float* Ap = A + (size_t)(m0 + lr) * Kn + lk;
    const float* Wp = W + (size_t)(n0 + lr) * Kn + lk;

    for (int k0 = 0; k0 < Kn; k0 += 16) {
        float4 a4 = *(const float4*)(Ap + k0);
        float4 b4 = *(const float4*)(Wp + k0);
        __syncthreads();
        sA[lr][lk] = a4.x; sA[lr][lk+1] = a4.y; sA[lr][lk+2] = a4.z; sA[lr][lk+3] = a4.w;
        sB[lr][lk] = b4.x; sB[lr][lk+1] = b4.y; sB[lr][lk+2] = b4.z; sB[lr][lk+3] = b4.w;
        __syncthreads();
        #pragma unroll
        for (int kk = 0; kk < 16; kk++) {
            float av[4], bv[4];
            #pragma unroll
            for (int i = 0; i < 4; i++) av[i] = sA[r0 + i][kk];
            #pragma unroll
            for (int c = 0; c < 4; c++) bv[c] = sB[j + (c << 4)][kk];
            #pragma unroll
            for (int i = 0; i < 4; i++)
                #pragma unroll
                for (int c = 0; c < 4; c++)
                    acc[i][c] += av[i] * bv[c];
        }
    }

    #pragma unroll
    for (int i = 0; i < 4; i++) {
        #pragma unroll
        for (int c = 0; c < 4; c++) {
            const int m = m0 + r0 + i;
            const int n = n0 + j + (c << 4);
            float v = acc[i][c] + bias[n];
            if (MODE == 1) {
                const size_t idx = (size_t)m * Nn + n;
                out[idx] = v + resid[idx];
            } else {
                const int b = m >> 11;          // L_ = 2048
                const int l = m & (L_ - 1);
                const int h = n >> 6;           // DH_ = 64
                const int d = n & 63;
                out[(((((size_t)b * H_ + h) << 11) + l) << 6) + d] = v;
            }
        }
    }
}

// ---------------- flash attention (fp32, online softmax) -------------------
// grid: (L/64, H, B), block 256. Each block: 64 q-rows, iterate 64-col k-tiles.
__global__ __launch_bounds__(256) void attn_kernel(
    const float* __restrict__ Qg, const float* __restrict__ Kg,
    const float* __restrict__ Vg, const unsigned char* __restrict__ mask,
    float* __restrict__ CTX)
{
    extern __shared__ float sm[];
    float* sQ = sm;
    float* sK = sm + 64 * AST;
    float* sV = sm + 2 * 64 * AST;
    float* sP = sm + 3 * 64 * AST;

    const int t  = threadIdx.x;
    const int qt = blockIdx.x;
    const int h  = blockIdx.y;
    const int b  = blockIdx.z;

    const float* Qb = Qg + (((size_t)b * H_ + h) * L_ + (qt << 6)) * DH_;
    const float* Kb = Kg + ((size_t)b * H_ + h) * L_ * DH_;
    const float* Vb = Vg + ((size_t)b * H_ + h) * L_ * DH_;

    // load Q tile (64x64) — float4, 16B-aligned (AST*4 = 272 bytes, 16B mult)
    #pragma unroll
    for (int i = 0; i < 4; i++) {
        int idx = t + (i << 8);
        int row = idx >> 4;
        int c4  = (idx & 15) << 2;
        *(float4*)&sQ[row * AST + c4] = *(const float4*)&Qb[(row << 6) + c4];
    }

    const int r0 = (t >> 4) << 2;
    const int j  = t & 15;

    float m_run[4], l_run[4], accO[4][4];
    #pragma unroll
    for (int i = 0; i < 4; i++) {
        m_run[i] = -1e30f; l_run[i] = 0.f;
        #pragma unroll
        for (int c = 0; c < 4; c++) accO[i][c] = 0.f;
    }

    const size_t mrow = ((size_t)b * L_ + (qt << 6) + r0) * L_;

    for (int kt = 0; kt < L_ / 64; kt++) {
        __syncthreads();   // prior PV reads of sK/sV done
        const float* Kt = Kb + ((size_t)kt << 6) * DH_;
        const float* Vt = Vb + ((size_t)kt << 6) * DH_;
        #pragma unroll
        for (int i = 0; i < 4; i++) {
            int idx = t + (i << 8);
            int row = idx >> 4;
            int c4  = (idx & 15) << 2;
            *(float4*)&sK[row * AST + c4] = *(const float4*)&Kt[(row << 6) + c4];
            *(float4*)&sV[row * AST + c4] = *(const float4*)&Vt[(row << 6) + c4];
        }
        __syncthreads();

        // S = Q K^T for 4x4 microtile; cols j, j+16, j+32, j+48 (bank-phase safe)
        float S[4][4] = {};
        #pragma unroll
        for (int d = 0; d < 64; d += 4) {
            float4 qv[4], kv[4];
            #pragma unroll
            for (int i = 0; i < 4; i++) qv[i] = *(const float4*)&sQ[(r0 + i) * AST + d];
            #pragma unroll
            for (int c = 0; c < 4; c++) kv[c] = *(const float4*)&sK[(j + (c << 4)) * AST + d];
            #pragma unroll
            for (int i = 0; i < 4; i++)
                #pragma unroll
                for (int c = 0; c < 4; c++)
                    S[i][c] += qv[i].x * kv[c].x + qv[i].y * kv[c].y
                             + qv[i].z * kv[c].z + qv[i].w * kv[c].w;
        }

        // scale (1/sqrt(DH)) + mask
        #pragma unroll
        for (int i = 0; i < 4; i++)
            #pragma unroll
            for (int c = 0; c < 4; c++) {
                float s = S[i][c] * 0.125f;
                if (mask[mrow + (size_t)i * L_ + (kt << 6) + j + (c << 4)]) s = -1e30f;
                S[i][c] = s;
            }

        // row max across the 16-lane column group
        float mt[4];
        #pragma unroll
        for (int i = 0; i < 4; i++)
            mt[i] = fmaxf(fmaxf(S[i][0], S[i][1]), fmaxf(S[i][2], S[i][3]));
        #pragma unroll
        for (int off = 8; off >= 1; off >>= 1)
            #pragma unroll
            for (int i = 0; i < 4; i++)
                mt[i] = fmaxf(mt[i], __shfl_xor_sync(0xffffffffu, mt[i], off));

        float alpha[4], rs[4];
        #pragma unroll
        for (int i = 0; i < 4; i++) {
            float mn = fmaxf(m_run[i], mt[i]);
            alpha[i] = __expf(m_run[i] - mn);
            m_run[i] = mn;
            rs[i] = 0.f;
            #pragma unroll
            for (int c = 0; c < 4; c++) {
                S[i][c] = __expf(S[i][c] - mn);
                rs[i] += S[i][c];
            }
        }
        #pragma unroll
        for (int off = 8; off >= 1; off >>= 1)
            #pragma unroll
            for (int i = 0; i < 4; i++)
                rs[i] += __shfl_xor_sync(0xffffffffu, rs[i], off);
        #pragma unroll
        for (int i = 0; i < 4; i++) {
            l_run[i] = l_run[i] * alpha[i] + rs[i];
            #pragma unroll
            for (int c = 0; c < 4; c++) accO[i][c] *= alpha[i];
        }

        // stage P
        #pragma unroll
        for (int i = 0; i < 4; i++)
            #pragma unroll
            for (int c = 0; c < 4; c++)
                sP[(r0 + i) * AST + j + (c << 4)] = S[i][c];
        __syncthreads();

        // O += P @ V
        #pragma unroll 4
        for (int jj = 0; jj < 64; jj++) {
            float pv[4], vv[4];
            #pragma unroll
            for (int i = 0; i < 4; i++) pv[i] = sP[(r0 + i) * AST + jj];
            #pragma unroll
            for (int c = 0; c < 4; c++) vv[c] = sV[jj * AST + j + (c << 4)];
            #pragma unroll
            for (int i = 0; i < 4; i++)
                #pragma unroll
                for (int c = 0; c < 4; c++)
                    accO[i][c] += pv[i] * vv[c];
        }
    }

    #pragma unroll
    for (int i = 0; i < 4; i++) {
        const int l = (qt << 6) + r0 + i;
        const float inv = 1.0f / l_run[i];
        #pragma unroll
        for (int c = 0; c < 4; c++)
            CTX[((size_t)b * L_ + l) * E_ + (h << 6) + j + (c << 4)] = accO[i][c] * inv;
    }
}

// ---------------- LayerNorm over E=1024, one row per block -----------------
__global__ __launch_bounds__(256) void ln_kernel(
    const float* __restrict__ X, const float* __restrict__ gamma,
    const float* __restrict__ beta, float* __restrict__ out)
{
    __shared__ float red[8];
    __shared__ float s_mu, s_rstd;
    const int row = blockIdx.x;
    const int t = threadIdx.x;

    float4 v = ((const float4*)(X + (size_t)row * E_))[t];
    float s = v.x + v.y + v.z + v.w;
    #pragma unroll
    for (int off = 16; off >= 1; off >>= 1) s += __shfl_xor_sync(0xffffffffu, s, off);
    if ((t & 31) == 0) red[t >> 5] = s;
    __syncthreads();
    if (t == 0) {
        float tot = 0.f;
        #pragma unroll
        for (int k = 0; k < 8; k++) tot += red[k];
        s_mu = tot * (1.0f / E_);
    }
    __syncthreads();
    const float mu = s_mu;

    float dx = v.x - mu, dy = v.y - mu, dz = v.z - mu, dw = v.w - mu;
    float sq = dx * dx + dy * dy + dz * dz + dw * dw;
    #pragma unroll
    for (int off = 16; off >= 1; off >>= 1) sq += __shfl_xor_sync(0xffffffffu, sq, off);
    __syncthreads();                       // protect red reuse
    if ((t & 31) == 0) red[t >> 5] = sq;
    __syncthreads();
    if (t == 0) {
        float tot = 0.f;
        #pragma unroll
        for (int k = 0; k < 8; k++) tot += red[k];
        s_rstd = rsqrtf(tot * (1.0f / E_) + 1e-6f);
    }
    __syncthreads();
    const float rstd = s_rstd;

    float4 g  = ((const float4*)gamma)[t];
    float4 be = ((const float4*)beta)[t];
    float4 o;
    o.x = dx * rstd * g.x + be.x;
    o.y = dy * rstd * g.y + be.y;
    o.z = dz * rstd * g.z + be.z;
    o.w = dw * rstd * g.w + be.w;
    ((float4*)(out + (size_t)row * E_))[t] = o;
}

// ---------------- launch ---------------------------------------------------
extern "C" void kernel_launch(void* const* d_in, const int* in_sizes, int n_in,
                              void* d_out, int out_size)
{
    const float* xq    = (const float*)d_in[0];
    const float* xk    = (const float*)d_in[1];
    const float* xv    = (const float*)d_in[2];
    const unsigned char* mask = (const unsigned char*)d_in[3];
    const float* Wq = (const float*)d_in[4];
    const float* bq = (const float*)d_in[5];
    const float* Wk = (const float*)d_in[6];
    const float* bk = (const float*)d_in[7];
    const float* Wv = (const float*)d_in[8];
    const float* bv = (const float*)d_in[9];
    const float* Wo = (const float*)d_in[10];
    const float* bo = (const float*)d_in[11];
    const float* gamma = (const float*)d_in[12];
    const float* beta  = (const float*)d_in[13];
    float* out = (float*)d_out;

    float *dQ, *dK, *dV, *dCTX, *dPROJ;
    cudaGetSymbolAddress((void**)&dQ,    g_Q);
    cudaGetSymbolAddress((void**)&dK,    g_K);
    cudaGetSymbolAddress((void**)&dV,    g_V);
    cudaGetSymbolAddress((void**)&dCTX,  g_CTX);
    cudaGetSymbolAddress((void**)&dPROJ, g_PROJ);

    cudaFuncSetAttribute(attn_kernel,
                         cudaFuncAttributeMaxDynamicSharedMemorySize, ATTN_SMEM);

    dim3 ggrid(E_ / 64, M_ / 64);

    gemm_kernel<0><<<ggrid, 256>>>(xq, Wq, bq, nullptr, dQ, E_, E_);
    gemm_kernel<0><<<ggrid, 256>>>(xk, Wk, bk, nullptr, dK, E_, E_);
    gemm_kernel<0><<<ggrid, 256>>>(xv, Wv, bv, nullptr, dV, E_, E_);

    attn_kernel<<<dim3(L_ / 64, H_, B_), 256, ATTN_SMEM>>>(dQ, dK, dV, mask, dCTX);

    gemm_kernel<1><<<ggrid, 256>>>(dCTX, Wo, bo, xq, dPROJ, E_, E_);

    ln_kernel<<<M_, 256>>>(dPROJ, gamma, beta, out);
}